// round 17
// baseline (speedup 1.0000x reference)
#include <cuda_runtime.h>
#include <cuda_bf16.h>
#include <cuda_fp16.h>
#include <cstdint>

#define BATCH  16
#define NPAT   1024
#define EMB    128
#define HEADS  8
#define ROWS_TOT (BATCH*NPAT)      /* 16384 */
#define INNERD   (EMB*HEADS)       /* 1024  */
#define FLTMAX 3.402823466e38f

// ---------------- scratch (static device allocations; allowed) ----------------
// All tiles PRE-SWIZZLED in the exact smem layout the consumers use. fp16 throughout.
__device__ uint4 g_xn [4194304/16];                        // xn  fp16 single [128 rt][128r][128k]
__device__ uint4 g_q  [33554432/16];                       // Q   fp16 single [128 bh][8 qt][128][128]
__device__ uint4 g_kh [33554432/16];                       // K   fp16 single [128 bh][16 jt][64][128]
__device__ uint4 g_vth[33554432/16];                       // Vt  fp16 single [128 bh][16 jt][128d][64s]
__device__ uint4 g_ao [33554432/16];                       // O   fp16 single [128 rt][128r][1024k]
__device__ uint4 g_wqh[786432/16],   g_wql[786432/16];     // wqkv^T fp16 hi/lo [3072 n][128 k]
__device__ uint4 g_wph[262144/16],   g_wpl[262144/16];     // wproj^T fp16 hi/lo [128 d][1024 k]

// ====================== PTX helpers ======================
__device__ __forceinline__ uint32_t smem_u32(const void* p) {
    uint32_t a;
    asm("{ .reg .u64 t; cvta.to.shared.u64 t, %1; cvt.u32.u64 %0, t; }" : "=r"(a) : "l"(p));
    return a;
}
__device__ __forceinline__ void ldsm4(uint32_t* r, uint32_t a) {
    asm volatile("ldmatrix.sync.aligned.m8n8.x4.shared.b16 {%0,%1,%2,%3}, [%4];"
        : "=r"(r[0]), "=r"(r[1]), "=r"(r[2]), "=r"(r[3]) : "r"(a));
}
__device__ __forceinline__ void mma16816h(float* d, const uint32_t* a, const uint32_t* b) {
    asm volatile("mma.sync.aligned.m16n8k16.row.col.f32.f16.f16.f32 "
        "{%0,%1,%2,%3}, {%4,%5,%6,%7}, {%8,%9}, {%0,%1,%2,%3};"
        : "+f"(d[0]), "+f"(d[1]), "+f"(d[2]), "+f"(d[3])
        : "r"(a[0]), "r"(a[1]), "r"(a[2]), "r"(a[3]), "r"(b[0]), "r"(b[1]));
}
__device__ __forceinline__ void cpa16(uint32_t dst, const void* src) {
    asm volatile("cp.async.cg.shared.global [%0], [%1], 16;" :: "r"(dst), "l"(src));
}
#define CPA_COMMIT() asm volatile("cp.async.commit_group;" ::: "memory")
#define CPA_WAIT(n)  asm volatile("cp.async.wait_group %0;" :: "n"(n) : "memory")

__device__ __forceinline__ uint32_t hpack(__half a, __half b) {
    __half2 t = __halves2half2(a, b);
    return *reinterpret_cast<uint32_t*>(&t);
}
__device__ __forceinline__ uint32_t hpack2(float a, float b) {
    return hpack(__float2half_rn(a), __float2half_rn(b));
}
__device__ __forceinline__ void hsplit2(float a, float b, uint32_t& hi, uint32_t& lo) {
    __half ha = __float2half_rn(a), hb = __float2half_rn(b);
    __half la = __float2half_rn(a - __half2float(ha));
    __half lb = __float2half_rn(b - __half2float(hb));
    hi = hpack(ha, hb); lo = hpack(la, lb);
}

// =============================== merged weight prep ===============================
// blocks 0..767: wqkv (196608 elems). blocks 768..1023: wproj (65536 elems).
__global__ void prep_w(const float* __restrict__ wq, const float* __restrict__ wp) {
    if (blockIdx.x < 768) {
        int idx = blockIdx.x*256 + threadIdx.x;
        int n = idx >> 6, kp = (idx & 63) << 1;
        float a = wq[kp*3072 + n], b = wq[(kp+1)*3072 + n];
        uint32_t hi, lo; hsplit2(a, b, hi, lo);
        uint32_t off = (uint32_t)(n*256 + (((kp>>3) ^ (n&7))<<4) + (kp&7)*2);
        *(uint32_t*)((char*)g_wqh + off) = hi;
        *(uint32_t*)((char*)g_wql + off) = lo;
    } else {
        int idx = (blockIdx.x - 768)*256 + threadIdx.x;
        int d = idx >> 9, kp = (idx & 511) << 1;
        float a = wp[kp*128 + d], b = wp[(kp+1)*128 + d];
        uint32_t hi, lo; hsplit2(a, b, hi, lo);
        uint32_t off = (uint32_t)(d*2048 + (((kp>>3) ^ (d&7))<<4) + (kp&7)*2);
        *(uint32_t*)((char*)g_wph + off) = hi;
        *(uint32_t*)((char*)g_wpl + off) = lo;
    }
}

// =============================== LayerNorm (warp-per-row, fp16 out) ===============================
__global__ void __launch_bounds__(256) ln_kernel(const float* __restrict__ x,
                                                 const float* __restrict__ w,
                                                 const float* __restrict__ b) {
    int wid = threadIdx.x >> 5, lane = threadIdx.x & 31;
    int row = blockIdx.x*8 + wid;
    float4 v = *(const float4*)&x[row*EMB + lane*4];
    float s = v.x + v.y + v.z + v.w;
    #pragma unroll
    for (int o = 16; o; o >>= 1) s += __shfl_xor_sync(0xffffffffu, s, o);
    float mean = s * (1.0f/EMB);
    float d0 = v.x - mean, d1 = v.y - mean, d2 = v.z - mean, d3 = v.w - mean;
    float q = d0*d0 + d1*d1 + d2*d2 + d3*d3;
    #pragma unroll
    for (int o = 16; o; o >>= 1) q += __shfl_xor_sync(0xffffffffu, q, o);
    float rinv = rsqrtf(q * (1.0f/EMB) + 1e-5f);
    float4 wv = *(const float4*)&w[lane*4];
    float4 bv = *(const float4*)&b[lane*4];
    float xn0 = d0*rinv*wv.x + bv.x, xn1 = d1*rinv*wv.y + bv.y;
    float xn2 = d2*rinv*wv.z + bv.z, xn3 = d3*rinv*wv.w + bv.w;
    int rt = row >> 7, rl = row & 127, dd = lane*4;
    uint32_t off = (uint32_t)(rt*32768 + rl*256 + (((dd>>3) ^ (rl&7))<<4) + (dd&7)*2);
    *(uint2*)((char*)g_xn + off) = make_uint2(hpack2(xn0, xn1), hpack2(xn2, xn3));
}

// =============================== QKV GEMM (fp16 2-term, 128-col tiles) ===============================
// grid (24 coltiles, 128 rowtiles). CTA: 128 rows x 128 cols, k=128.
// Each CTA's col range is exactly one section+head (dbase always 0).
// smem: A 32KB @0, BH 32KB @32768, BL 32KB @65536
#define QKV_SMEM 98304
__global__ void __launch_bounds__(256, 2) qkv_mma(const float* __restrict__ scale) {
    extern __shared__ char smc[];
    uint32_t sb = smem_u32(smc);
    int tid = threadIdx.x, w = tid >> 5, L = tid & 31;
    int rowbase = blockIdx.y * 128;
    int colbase = blockIdx.x * 128;

    {
        const char* ax  = (const char*)g_xn  + (size_t)blockIdx.y*32768;
        const char* bxh = (const char*)g_wqh + (size_t)blockIdx.x*32768;
        const char* bxl = (const char*)g_wql + (size_t)blockIdx.x*32768;
        #pragma unroll
        for (int it = 0; it < 8; it++) {
            uint32_t o = (uint32_t)(it*256 + tid)*16;
            cpa16(sb + o,         ax + o);
            cpa16(sb + 32768 + o, bxh + o);
            cpa16(sb + 65536 + o, bxl + o);
        }
        CPA_COMMIT(); CPA_WAIT(0);
    }
    __syncthreads();

    int l7 = L & 7;
    int rowA = (w << 4) + ((L >> 3) & 1)*8 + l7;
    int cA = L >> 4;
    uint32_t aB = sb + rowA*256;
    int rB = (L & 7) + ((L >> 4) & 1)*8;
    int csel = (L >> 3) & 1;

    float acc[16][4];
    #pragma unroll
    for (int nb = 0; nb < 16; nb++) { acc[nb][0]=0.f; acc[nb][1]=0.f; acc[nb][2]=0.f; acc[nb][3]=0.f; }

    #pragma unroll
    for (int kc = 0; kc < 8; kc++) {
        uint32_t a4[4];
        uint32_t ap = (uint32_t)(((kc*2 + cA) ^ l7) << 4);
        ldsm4(a4, aB + ap);
        uint32_t cp = (uint32_t)(((kc*2 + csel) ^ l7) << 4);
        #pragma unroll
        for (int nbp = 0; nbp < 8; nbp++) {
            uint32_t bh4[4], bl4[4];
            uint32_t bo = (uint32_t)((nbp*16 + rB)*256) + cp;
            ldsm4(bh4, sb + 32768 + bo);
            ldsm4(bl4, sb + 65536 + bo);
            mma16816h(acc[2*nbp],   a4, bh4);     mma16816h(acc[2*nbp],   a4, bl4);
            mma16816h(acc[2*nbp+1], a4, bh4+2);   mma16816h(acc[2*nbp+1], a4, bl4+2);
        }
    }

    int g = L >> 2, t2 = (L & 3)*2;
    int r0 = (w << 4) + g, r1 = r0 + 8;
    int section = colbase >> 10, h = (colbase & 1023) >> 7;
    int b = rowbase >> 10, n0 = rowbase & 1023;
    int bh = b*HEADS + h;

    if (section == 0) {
        float sc = scale[h];
        char* dq = (char*)g_q + (size_t)(bh*8 + (n0 >> 7))*32768;
        #pragma unroll
        for (int nb = 0; nb < 16; nb++) {
            uint32_t o0 = (uint32_t)(r0*256 + ((nb ^ (r0&7))<<4) + t2*2);
            *(uint32_t*)(dq + o0) = hpack2(acc[nb][0]*sc, acc[nb][1]*sc);
            uint32_t o1 = (uint32_t)(r1*256 + ((nb ^ (r1&7))<<4) + t2*2);
            *(uint32_t*)(dq + o1) = hpack2(acc[nb][2]*sc, acc[nb][3]*sc);
        }
    } else if (section == 1) {
        char* dh = (char*)g_kh + (size_t)(bh*16 + (n0 >> 6))*16384;
        int t0 = (r0 >> 6)*16384, rl0 = r0 & 63;
        int t1 = (r1 >> 6)*16384, rl1 = r1 & 63;
        #pragma unroll
        for (int nb = 0; nb < 16; nb++) {
            uint32_t o0 = (uint32_t)(t0 + rl0*256 + ((nb ^ (rl0&7))<<4) + t2*2);
            *(uint32_t*)(dh + o0) = hpack2(acc[nb][0], acc[nb][1]);
            uint32_t o1 = (uint32_t)(t1 + rl1*256 + ((nb ^ (rl1&7))<<4) + t2*2);
            *(uint32_t*)(dh + o1) = hpack2(acc[nb][2], acc[nb][3]);
        }
    } else {
        // V: stage fp32 [128 s][132], then pre-swizzled Vt (2 jt tiles)
        __syncthreads();
        float* stg = (float*)smc;
        #pragma unroll
        for (int nb = 0; nb < 16; nb++) {
            int dl0 = nb*8 + t2;
            stg[r0*132 + dl0] = acc[nb][0];  stg[r0*132 + dl0 + 1] = acc[nb][1];
            stg[r1*132 + dl0] = acc[nb][2];  stg[r1*132 + dl0 + 1] = acc[nb][3];
        }
        __syncthreads();
        char* vh = (char*)g_vth + (size_t)(bh*16 + (n0 >> 6))*16384;
        #pragma unroll
        for (int it = 0; it < 8; it++) {
            int e = it*256 + tid, dloc = e & 127, c8 = e >> 7;   // c8 0..15 over 128 s
            uint32_t hi4[4];
            #pragma unroll
            for (int p = 0; p < 4; p++)
                hi4[p] = hpack2(stg[(c8*8 + 2*p)*132 + dloc], stg[(c8*8 + 2*p + 1)*132 + dloc]);
            uint32_t off = (uint32_t)((c8 >> 3)*16384 + dloc*128 + (((c8 & 7) ^ (dloc&7))<<4));
            *(uint4*)(vh + off) = make_uint4(hi4[0], hi4[1], hi4[2], hi4[3]);
        }
    }
}

// ====================== fp16 flash attention (2 CTA/SM) ======================
// grid (8 qt, 128 bh), 256 thr. S = Q·K, O = P·V, all single fp16.
#define AQ 0
#define ABUF(b) (32768 + (b)*32768)     /* K 16KB, V 16KB */
#define SMEM_ATTN 98304
__global__ void __launch_bounds__(256, 2) attn_mma() {
    extern __shared__ char smc[];
    uint32_t sb = smem_u32(smc);
    int tid = threadIdx.x, w = tid >> 5, L = tid & 31;
    int qt = blockIdx.x, bh = blockIdx.y;
    int qbase = qt * 128;

    {
        const char* qg = (const char*)g_q + (size_t)(bh*8 + qt)*32768;
        #pragma unroll
        for (int it = 0; it < 8; it++) {
            uint32_t o = (uint32_t)(it*256 + tid)*16;
            cpa16(sb + AQ + o, qg + o);
        }
        const char* kh = (const char*)g_kh + (size_t)(bh*16)*16384;
        const char* vh = (const char*)g_vth + (size_t)(bh*16)*16384;
        uint32_t dst = sb + ABUF(0);
        #pragma unroll
        for (int it = 0; it < 4; it++) {
            uint32_t o = (uint32_t)(it*256 + tid)*16;
            cpa16(dst + o,         kh + o);
            cpa16(dst + 16384 + o, vh + o);
        }
        CPA_COMMIT();
    }

    int l7 = L & 7;
    int rowA = (w << 4) + ((L >> 3) & 1)*8 + l7;
    int cA = L >> 4;
    uint32_t aB = sb + AQ + rowA*256;
    int rB = (L & 7) + ((L >> 4) & 1)*8;
    int csel = (L >> 3) & 1;
    int g = L >> 2, t2 = (L & 3)*2;
    int rg0 = qbase + (w << 4) + g, rg1 = rg0 + 8;

    float m0 = -FLTMAX, m1 = -FLTMAX, ls0 = 0.f, ls1 = 0.f;
    float O[16][4];
    #pragma unroll
    for (int nb = 0; nb < 16; nb++) { O[nb][0]=0.f; O[nb][1]=0.f; O[nb][2]=0.f; O[nb][3]=0.f; }

    #pragma unroll 1
    for (int j = 0; j < 16; j++) {
        if (j < 15) {
            int jn = j + 1;
            const char* kh = (const char*)g_kh + (size_t)(bh*16 + jn)*16384;
            const char* vh = (const char*)g_vth + (size_t)(bh*16 + jn)*16384;
            uint32_t dst = sb + ABUF(jn & 1);
            #pragma unroll
            for (int it = 0; it < 4; it++) {
                uint32_t o = (uint32_t)(it*256 + tid)*16;
                cpa16(dst + o,         kh + o);
                cpa16(dst + 16384 + o, vh + o);
            }
            CPA_COMMIT(); CPA_WAIT(1);
        } else {
            CPA_WAIT(0);
        }
        __syncthreads();
        uint32_t kb = sb + ABUF(j & 1);
        uint32_t vb = kb + 16384;

        // ---- S = Q K : m16 x n64 per warp, k=128 ----
        float S[8][4];
        #pragma unroll
        for (int nb = 0; nb < 8; nb++) { S[nb][0]=0.f; S[nb][1]=0.f; S[nb][2]=0.f; S[nb][3]=0.f; }
        #pragma unroll
        for (int kc = 0; kc < 8; kc++) {
            uint32_t a4[4];
            uint32_t ap = (uint32_t)(((kc*2 + cA) ^ l7) << 4);
            ldsm4(a4, aB + ap);
            uint32_t cp = (uint32_t)(((kc*2 + csel) ^ l7) << 4);
            #pragma unroll
            for (int nbp = 0; nbp < 4; nbp++) {
                uint32_t bk[4];
                uint32_t bo = (uint32_t)((nbp*16 + rB)*256) + cp;
                ldsm4(bk, kb + bo);
                mma16816h(S[2*nbp],   a4, bk);
                mma16816h(S[2*nbp+1], a4, bk+2);
            }
        }

        if ((j >> 1) == qt) {
            int colbase = j*64;
            #pragma unroll
            for (int nb = 0; nb < 8; nb++) {
                int c0 = colbase + nb*8 + t2;
                if (c0     == rg0) S[nb][0] = -FLTMAX;
                if (c0 + 1 == rg0) S[nb][1] = -FLTMAX;
                if (c0     == rg1) S[nb][2] = -FLTMAX;
                if (c0 + 1 == rg1) S[nb][3] = -FLTMAX;
            }
        }

        // ---- online softmax ----
        float rmax0 = -FLTMAX, rmax1 = -FLTMAX;
        #pragma unroll
        for (int nb = 0; nb < 8; nb++) {
            rmax0 = fmaxf(rmax0, fmaxf(S[nb][0], S[nb][1]));
            rmax1 = fmaxf(rmax1, fmaxf(S[nb][2], S[nb][3]));
        }
        rmax0 = fmaxf(rmax0, __shfl_xor_sync(0xffffffffu, rmax0, 1));
        rmax0 = fmaxf(rmax0, __shfl_xor_sync(0xffffffffu, rmax0, 2));
        rmax1 = fmaxf(rmax1, __shfl_xor_sync(0xffffffffu, rmax1, 1));
        rmax1 = fmaxf(rmax1, __shfl_xor_sync(0xffffffffu, rmax1, 2));
        float mn0 = fmaxf(m0, rmax0), mn1 = fmaxf(m1, rmax1);
        float cr0 = __expf(m0 - mn0), cr1 = __expf(m1 - mn1);
        m0 = mn0; m1 = mn1;
        float rs0 = 0.f, rs1 = 0.f;
        #pragma unroll
        for (int nb = 0; nb < 8; nb++) {
            S[nb][0] = __expf(S[nb][0] - mn0); rs0 += S[nb][0];
            S[nb][1] = __expf(S[nb][1] - mn0); rs0 += S[nb][1];
            S[nb][2] = __expf(S[nb][2] - mn1); rs1 += S[nb][2];
            S[nb][3] = __expf(S[nb][3] - mn1); rs1 += S[nb][3];
        }
        rs0 += __shfl_xor_sync(0xffffffffu, rs0, 1);
        rs0 += __shfl_xor_sync(0xffffffffu, rs0, 2);
        rs1 += __shfl_xor_sync(0xffffffffu, rs1, 1);
        rs1 += __shfl_xor_sync(0xffffffffu, rs1, 2);
        ls0 = ls0*cr0 + rs0;
        ls1 = ls1*cr1 + rs1;
        #pragma unroll
        for (int nb = 0; nb < 16; nb++) {
            O[nb][0] *= cr0;  O[nb][1] *= cr0;
            O[nb][2] *= cr1;  O[nb][3] *= cr1;
        }

        // ---- O += P V ----
        #pragma unroll
        for (int kc = 0; kc < 4; kc++) {
            uint32_t ah[4];
            ah[0] = hpack2(S[2*kc][0],   S[2*kc][1]);
            ah[1] = hpack2(S[2*kc][2],   S[2*kc][3]);
            ah[2] = hpack2(S[2*kc+1][0], S[2*kc+1][1]);
            ah[3] = hpack2(S[2*kc+1][2], S[2*kc+1][3]);
            uint32_t cp = (uint32_t)(((kc*2 + csel) ^ l7) << 4);
            #pragma unroll
            for (int nbp = 0; nbp < 8; nbp++) {
                uint32_t v4[4];
                uint32_t bo = (uint32_t)((nbp*16 + rB)*128) + cp;
                ldsm4(v4, vb + bo);
                mma16816h(O[2*nbp],   ah, v4);
                mma16816h(O[2*nbp+1], ah, v4+2);
            }
        }
        __syncthreads();
    }

    // ---- epilogue: normalize, write single fp16 pre-swizzled O tiles for proj ----
    float inv0 = 1.0f / ls0, inv1 = 1.0f / ls1;
    int bb = bh >> 3, h = bh & 7;
    int rowtile = bb*8 + qt;
    int rl0 = (w << 4) + g, rl1 = rl0 + 8;
    char* ao = (char*)g_ao + (size_t)rowtile*262144;
    #pragma unroll
    for (int nb = 0; nb < 16; nb++) {
        int c16 = h*16 + nb;
        uint32_t o0 = (uint32_t)(rl0*2048 + ((c16 ^ (rl0&7))<<4) + t2*2);
        *(uint32_t*)(ao + o0) = hpack2(O[nb][0]*inv0, O[nb][1]*inv0);
        uint32_t o1 = (uint32_t)(rl1*2048 + ((c16 ^ (rl1&7))<<4) + t2*2);
        *(uint32_t*)(ao + o1) = hpack2(O[nb][2]*inv1, O[nb][3]*inv1);
    }
}

// =============================== Output projection (fp16 2-term, double-buffered) ===============================
#define PROJ_SMEM 98304
__global__ void __launch_bounds__(256, 1) proj_mma(const float* __restrict__ bias,
                                                   float* __restrict__ out) {
    extern __shared__ char smc[];
    uint32_t sb = smem_u32(smc);
    int tid = threadIdx.x, w = tid >> 5, L = tid & 31;
    int rowtile = blockIdx.x;
    const char* ao = (const char*)g_ao + (size_t)rowtile*262144;

    int l7 = L & 7;
    int rowA = (w << 4) + ((L >> 3) & 1)*8 + l7;
    int cA = L >> 4;
    int rB = (L & 7) + ((L >> 4) & 1)*8;
    int csel = (L >> 3) & 1;
    int g = L >> 2, t2 = (L & 3)*2;

    auto prefetch = [&](int kb, int st) {
        uint32_t base = sb + st*49152;
        #pragma unroll
        for (int it = 0; it < 4; it++) {
            int e = it*256 + tid, r = e >> 3, jj = e & 7;
            uint32_t go = (uint32_t)(r*2048 + kb*128 + ((jj ^ (r&7))<<4));
            uint32_t so = (uint32_t)(r*128 + ((jj ^ (r&7))<<4));
            cpa16(base + so,          ao + go);
            cpa16(base + 16384 + so,  (const char*)g_wph + go);
            cpa16(base + 32768 + so,  (const char*)g_wpl + go);
        }
        CPA_COMMIT();
    };

    float acc[16][4];
    #pragma unroll
    for (int nb = 0; nb < 16; nb++) { acc[nb][0]=0.f; acc[nb][1]=0.f; acc[nb][2]=0.f; acc[nb][3]=0.f; }

    prefetch(0, 0);
    #pragma unroll 1
    for (int kb = 0; kb < 16; kb++) {
        if (kb < 15) { prefetch(kb + 1, (kb + 1) & 1); CPA_WAIT(1); }
        else          CPA_WAIT(0);
        __syncthreads();
        uint32_t base = sb + (kb & 1)*49152;
        uint32_t aB = base + rowA*128;
        #pragma unroll
        for (int kc = 0; kc < 4; kc++) {
            uint32_t a4[4];
            uint32_t ap = (uint32_t)(((kc*2 + cA) ^ l7) << 4);
            ldsm4(a4, aB + ap);
            uint32_t cp = (uint32_t)(((kc*2 + csel) ^ l7) << 4);
            #pragma unroll
            for (int nbp = 0; nbp < 8; nbp++) {
                uint32_t bh4[4], bl4[4];
                uint32_t bo = (uint32_t)((nbp*16 + rB)*128) + cp;
                ldsm4(bh4, base + 16384 + bo);  ldsm4(bl4, base + 32768 + bo);
                mma16816h(acc[2*nbp],   a4, bh4);    mma16816h(acc[2*nbp],   a4, bl4);
                mma16816h(acc[2*nbp+1], a4, bh4+2);  mma16816h(acc[2*nbp+1], a4, bl4+2);
            }
        }
        __syncthreads();
    }

    int r0 = rowtile*128 + (w << 4) + g, r1 = r0 + 8;
    #pragma unroll
    for (int nb = 0; nb < 16; nb++) {
        int col = nb*8 + t2;
        float b0 = bias[col], b1 = bias[col + 1];
        *(float2*)&out[r0*128 + col] = make_float2(acc[nb][0] + b0, acc[nb][1] + b1);
        *(float2*)&out[r1*128 + col] = make_float2(acc[nb][2] + b0, acc[nb][3] + b1);
    }
}

// =============================== launch ===============================
extern "C" void kernel_launch(void* const* d_in, const int* in_sizes, int n_in,
                              void* d_out, int out_size) {
    const float* x      = (const float*)d_in[0];
    const float* ln_w   = (const float*)d_in[1];
    const float* ln_b   = (const float*)d_in[2];
    const float* w_qkv  = (const float*)d_in[3];
    const float* scale  = (const float*)d_in[4];
    const float* w_proj = (const float*)d_in[5];
    const float* b_proj = (const float*)d_in[6];
    float* out = (float*)d_out;

    cudaFuncSetAttribute(qkv_mma,  cudaFuncAttributeMaxDynamicSharedMemorySize, QKV_SMEM);
    cudaFuncSetAttribute(attn_mma, cudaFuncAttributeMaxDynamicSharedMemorySize, SMEM_ATTN);
    cudaFuncSetAttribute(proj_mma, cudaFuncAttributeMaxDynamicSharedMemorySize, PROJ_SMEM);

    prep_w   <<<1024, 256>>>(w_qkv, w_proj);
    ln_kernel<<<2048, 256>>>(x, ln_w, ln_b);
    qkv_mma  <<<dim3(24, 128), 256, QKV_SMEM>>>(scale);
    attn_mma <<<dim3(8, 128), 256, SMEM_ATTN>>>();
    proj_mma <<<128, 256, PROJ_SMEM>>>(b_proj, out);
}